// round 2
// baseline (speedup 1.0000x reference)
#include <cuda_runtime.h>
#include <cstdint>

// Problem constants
#define OBS  194
#define HID  64
#define NACT 5
#define NEV  3
#define TM   128      // rows per CTA
#define KP   208      // K padded to 13*16
#define KC   16       // K chunk
#define NCH  13       // chunks
#define XSP  132      // padded row stride for transposed x / H1T (floats, mult of 4)

// Shared layout (float offsets)
#define W1P_OFF 0                       // 208*128 = 26624
#define W2P_OFF 26624                   // 64*128  = 8192
#define B1_OFF  34816                   // 128
#define B2_OFF  34944                   // 128
#define WH_OFF  35072                   // 960
#define BH_OFF  36032                   // 16
#define WC3_OFF 36048                   // 64
#define BC3_OFF 36112                   // 4
#define XS_OFF  36116                   // 2 * 16 * 132 = 4224
#define H1T_OFF 40340                   // 128 * 132 = 16896
#define TOT_F   57236
#define SMEM_BYTES (TOT_F * 4)          // 228944 <= 232448

__device__ __forceinline__ unsigned long long dup_f32(float v) {
    unsigned long long d;
    unsigned int u = __float_as_uint(v);
    asm("mov.b64 %0, {%1, %1};" : "=l"(d) : "r"(u));
    return d;
}
__device__ __forceinline__ void unpack2(unsigned long long d, float& lo, float& hi) {
    unsigned int a, b;
    asm("mov.b64 {%0, %1}, %2;" : "=r"(a), "=r"(b) : "l"(d));
    lo = __uint_as_float(a); hi = __uint_as_float(b);
}
#define FMA2(d, a, b) asm("fma.rn.f32x2 %0, %1, %2, %0;" : "+l"(d) : "l"(a), "l"(b))

__global__ void __launch_bounds__(256, 1)
agent_fused_kernel(const float* __restrict__ x, const int* __restrict__ action,
                   const float* __restrict__ W1, const float* __restrict__ b1,
                   const float* __restrict__ W2, const float* __restrict__ b2,
                   const float* __restrict__ Wh, const float* __restrict__ bh,
                   const float* __restrict__ Wc1, const float* __restrict__ bc1,
                   const float* __restrict__ Wc2, const float* __restrict__ bc2,
                   const float* __restrict__ Wc3, const float* __restrict__ bc3,
                   float* __restrict__ out, int B)
{
    extern __shared__ float smem[];
    float* w1p   = smem + W1P_OFF;
    float* w2p   = smem + W2P_OFF;
    float* bias1 = smem + B1_OFF;
    float* bias2 = smem + B2_OFF;
    float* whs   = smem + WH_OFF;
    float* bhs   = smem + BH_OFF;
    float* wc3s  = smem + WC3_OFF;
    float* bc3s  = smem + BC3_OFF;
    float* xs    = smem + XS_OFF;      // [2][16][132]
    float* H1T   = smem + H1T_OFF;     // [128 cols][132] (row index = sample in tile)

    const int tid = threadIdx.x;
    const int tc  = tid & 15;          // col group 0..15
    const int tr  = tid >> 4;          // row group 0..15
    const int R   = tr * 8;
    const int C   = tc * 8;
    const int b0  = blockIdx.x * TM;

    // ---- stage weights ----
    for (int i = tid; i < OBS * HID; i += 256) {
        int k = i >> 6, c = i & 63;
        w1p[k * 128 + c]      = W1[i];
        w1p[k * 128 + 64 + c] = Wc1[i];
    }
    for (int i = tid; i < (KP - OBS) * 128; i += 256) w1p[OBS * 128 + i] = 0.f;
    for (int i = tid; i < HID * HID; i += 256) {
        int k = i >> 6, c = i & 63;
        w2p[k * 128 + c]      = W2[i];
        w2p[k * 128 + 64 + c] = Wc2[i];
    }
    if (tid < 64) {
        bias1[tid] = b1[tid];  bias1[64 + tid] = bc1[tid];
        bias2[tid] = b2[tid];  bias2[64 + tid] = bc2[tid];
        wc3s[tid]  = Wc3[tid];
    }
    for (int i = tid; i < NEV * HID * NACT; i += 256) whs[i] = Wh[i];
    if (tid < NEV * NACT) bhs[tid] = bh[tid];
    if (tid == 0) bc3s[0] = bc3[0];

    // ---- preload x chunk 0 (transposed into xs[0]) ----
    {
        float v[8];
        #pragma unroll
        for (int i = 0; i < 8; i++) {
            int idx = tid + i * 256;
            int row = idx >> 4, kk = idx & 15;
            v[i] = (kk < OBS && (b0 + row) < B) ? x[(size_t)(b0 + row) * OBS + kk] : 0.f;
        }
        __syncthreads();   // also covers weight staging
        #pragma unroll
        for (int i = 0; i < 8; i++) {
            int idx = tid + i * 256;
            xs[(idx & 15) * XSP + (idx >> 4)] = v[i];
        }
        __syncthreads();
    }

    unsigned long long acc[8][4];
    #pragma unroll
    for (int r = 0; r < 8; r++)
        #pragma unroll
        for (int j = 0; j < 4; j++) acc[r][j] = 0ull;

    // ---- GEMM1: [TM x KP] @ [KP x 128] (W1 | Wc1), x streamed ----
    for (int ch = 0; ch < NCH; ch++) {
        const int k0 = ch * KC;
        float nv[8];
        if (ch < NCH - 1) {
            const int kn = k0 + KC;
            #pragma unroll
            for (int i = 0; i < 8; i++) {
                int idx = tid + i * 256;
                int row = idx >> 4, kk = idx & 15, kg = kn + kk;
                nv[i] = (kg < OBS && (b0 + row) < B) ? x[(size_t)(b0 + row) * OBS + kg] : 0.f;
            }
        }
        const float* xb = xs + (ch & 1) * (KC * XSP);
        #pragma unroll
        for (int kk = 0; kk < KC; kk++) {
            float4 a0 = *(const float4*)(xb + kk * XSP + R);
            float4 a1 = *(const float4*)(xb + kk * XSP + R + 4);
            const float* wr = w1p + (k0 + kk) * 128 + C;
            ulonglong2 w0 = *(const ulonglong2*)wr;
            ulonglong2 w1v = *(const ulonglong2*)(wr + 4);
            unsigned long long xd[8];
            xd[0] = dup_f32(a0.x); xd[1] = dup_f32(a0.y);
            xd[2] = dup_f32(a0.z); xd[3] = dup_f32(a0.w);
            xd[4] = dup_f32(a1.x); xd[5] = dup_f32(a1.y);
            xd[6] = dup_f32(a1.z); xd[7] = dup_f32(a1.w);
            #pragma unroll
            for (int r = 0; r < 8; r++) {
                FMA2(acc[r][0], xd[r], w0.x);
                FMA2(acc[r][1], xd[r], w0.y);
                FMA2(acc[r][2], xd[r], w1v.x);
                FMA2(acc[r][3], xd[r], w1v.y);
            }
        }
        __syncthreads();
        if (ch < NCH - 1) {
            float* xw = xs + ((ch + 1) & 1) * (KC * XSP);
            #pragma unroll
            for (int i = 0; i < 8; i++) {
                int idx = tid + i * 256;
                xw[(idx & 15) * XSP + (idx >> 4)] = nv[i];
            }
        }
        __syncthreads();
    }

    // ---- epilogue 1: tanh + bias, transpose into H1T[col][row] ----
    #pragma unroll
    for (int j = 0; j < 4; j++) {
        const int c0 = C + 2 * j, c1 = c0 + 1;
        float f0[8], f1[8];
        #pragma unroll
        for (int r = 0; r < 8; r++) {
            float lo, hi; unpack2(acc[r][j], lo, hi);
            f0[r] = tanhf(lo + bias1[c0]);
            f1[r] = tanhf(hi + bias1[c1]);
        }
        *(float4*)(H1T + c0 * XSP + R)     = make_float4(f0[0], f0[1], f0[2], f0[3]);
        *(float4*)(H1T + c0 * XSP + R + 4) = make_float4(f0[4], f0[5], f0[6], f0[7]);
        *(float4*)(H1T + c1 * XSP + R)     = make_float4(f1[0], f1[1], f1[2], f1[3]);
        *(float4*)(H1T + c1 * XSP + R + 4) = make_float4(f1[4], f1[5], f1[6], f1[7]);
    }
    __syncthreads();

    // ---- GEMM2: block-diagonal layer 2 (actor cols<64 use W2, critic use Wc2) ----
    #pragma unroll
    for (int r = 0; r < 8; r++)
        #pragma unroll
        for (int j = 0; j < 4; j++) acc[r][j] = 0ull;

    const int koff = (tc < 8) ? 0 : 64;
    #pragma unroll 8
    for (int k = 0; k < HID; k++) {
        const float* ar = H1T + (koff + k) * XSP + R;
        float4 a0 = *(const float4*)ar;
        float4 a1 = *(const float4*)(ar + 4);
        const float* wr = w2p + k * 128 + C;
        ulonglong2 w0 = *(const ulonglong2*)wr;
        ulonglong2 w1v = *(const ulonglong2*)(wr + 4);
        unsigned long long xd[8];
        xd[0] = dup_f32(a0.x); xd[1] = dup_f32(a0.y);
        xd[2] = dup_f32(a0.z); xd[3] = dup_f32(a0.w);
        xd[4] = dup_f32(a1.x); xd[5] = dup_f32(a1.y);
        xd[6] = dup_f32(a1.z); xd[7] = dup_f32(a1.w);
        #pragma unroll
        for (int r = 0; r < 8; r++) {
            FMA2(acc[r][0], xd[r], w0.x);
            FMA2(acc[r][1], xd[r], w0.y);
            FMA2(acc[r][2], xd[r], w1v.x);
            FMA2(acc[r][3], xd[r], w1v.y);
        }
    }
    __syncthreads();   // everyone done reading H1T before overwrite

    // ---- epilogue 2: feat = tanh + bias2, write back into H1T ----
    #pragma unroll
    for (int j = 0; j < 4; j++) {
        const int c0 = C + 2 * j, c1 = c0 + 1;
        float f0[8], f1[8];
        #pragma unroll
        for (int r = 0; r < 8; r++) {
            float lo, hi; unpack2(acc[r][j], lo, hi);
            f0[r] = tanhf(lo + bias2[c0]);
            f1[r] = tanhf(hi + bias2[c1]);
        }
        *(float4*)(H1T + c0 * XSP + R)     = make_float4(f0[0], f0[1], f0[2], f0[3]);
        *(float4*)(H1T + c0 * XSP + R + 4) = make_float4(f0[4], f0[5], f0[6], f0[7]);
        *(float4*)(H1T + c1 * XSP + R)     = make_float4(f1[0], f1[1], f1[2], f1[3]);
        *(float4*)(H1T + c1 * XSP + R + 4) = make_float4(f1[4], f1[5], f1[6], f1[7]);
    }
    __syncthreads();

    // ---- per-row head: routing, log-softmax, entropy, critic value ----
    if (tid < TM) {
        const int r = tid;
        const int b = b0 + r;
        if (b < B) {
            const float* xr = x + (size_t)b * OBS;
            float x0 = xr[0], x1 = xr[1], x2 = xr[2];
            int ev = 0; float bv = x0;
            if (x1 > bv) { ev = 1; bv = x1; }
            if (x2 > bv) { ev = 2; }

            float lg[NACT];
            const float* bhp = bhs + ev * NACT;
            #pragma unroll
            for (int a = 0; a < NACT; a++) lg[a] = bhp[a];
            const float* whp = whs + ev * (HID * NACT);
            #pragma unroll 4
            for (int c = 0; c < HID; c++) {
                float f = H1T[c * XSP + r];
                const float* w = whp + c * NACT;
                lg[0] += f * w[0]; lg[1] += f * w[1]; lg[2] += f * w[2];
                lg[3] += f * w[3]; lg[4] += f * w[4];
            }
            float m = lg[0];
            #pragma unroll
            for (int a = 1; a < NACT; a++) m = fmaxf(m, lg[a]);
            float s = 0.f;
            #pragma unroll
            for (int a = 0; a < NACT; a++) s += expf(lg[a] - m);
            float lse = logf(s);
            float ent = 0.f;
            #pragma unroll
            for (int a = 0; a < NACT; a++) {
                float lp = lg[a] - m - lse;
                ent -= expf(lp) * lp;
            }
            int act = action[b];
            float logp = lg[act] - m - lse;

            float v = bc3s[0];
            #pragma unroll 8
            for (int c = 0; c < HID; c++) v += H1T[(64 + c) * XSP + r] * wc3s[c];

            out[b]                 = (float)act;
            out[(size_t)B + b]     = logp;
            out[(size_t)2 * B + b] = ent;
            out[(size_t)3 * B + b] = v;
        }
    }
}

extern "C" void kernel_launch(void* const* d_in, const int* in_sizes, int n_in,
                              void* d_out, int out_size)
{
    const float* x      = (const float*)d_in[0];
    const int*   action = (const int*)  d_in[1];
    const float* W1     = (const float*)d_in[2];
    const float* b1     = (const float*)d_in[3];
    const float* W2     = (const float*)d_in[4];
    const float* b2     = (const float*)d_in[5];
    const float* Wh     = (const float*)d_in[6];
    const float* bh     = (const float*)d_in[7];
    const float* Wc1    = (const float*)d_in[8];
    const float* bc1    = (const float*)d_in[9];
    const float* Wc2    = (const float*)d_in[10];
    const float* bc2    = (const float*)d_in[11];
    const float* Wc3    = (const float*)d_in[12];
    const float* bc3    = (const float*)d_in[13];
    float* out = (float*)d_out;

    const int B = in_sizes[1];   // action count = batch
    (void)n_in; (void)out_size;

    cudaFuncSetAttribute(agent_fused_kernel,
                         cudaFuncAttributeMaxDynamicSharedMemorySize, SMEM_BYTES);

    const int grid = (B + TM - 1) / TM;
    agent_fused_kernel<<<grid, 256, SMEM_BYTES>>>(
        x, action, W1, b1, W2, b2, Wh, bh, Wc1, bc1, Wc2, bc2, Wc3, bc3, out, B);
}